// round 15
// baseline (speedup 1.0000x reference)
#include <cuda_runtime.h>
#include <cuda_fp16.h>
#include <math.h>
#include <stdint.h>

#define SEQ 2048
#define DIM 4096
#define NH 32
#define NKV 8
#define HD 128
#define KVDIM 1024
#define NQKV (DIM + 2 * KVDIM)    // 6144 fused projection width

// Scratch (allocation-free rule: device globals)
__device__ __half g_Q16[SEQ * DIM];         // roped+scaled Q (base-2 domain)
__device__ __half g_K16[SEQ * KVDIM];       // roped K, fp16
__device__ __half g_V16[SEQ * KVDIM];       // V, fp16
__device__ __half g_vT[KVDIM * SEQ];        // V^T fp16 [KVDIM][SEQ]
__device__ __half g_attn16[SEQ * DIM];      // flash output, fp16
__device__ __half g_x16[SEQ * DIM];         // x, fp16
__device__ __half g_wqkvT[NQKV * DIM];      // [Wq^T; Wk^T; Wv^T] fp16
__device__ __half g_woT[DIM * DIM];

// ---------------------------------------------------------------------------
// Helpers
// ---------------------------------------------------------------------------
__device__ __forceinline__ void mma_f16(float c[4], const uint32_t a[4],
                                        const uint32_t b[2]) {
    asm volatile(
        "mma.sync.aligned.m16n8k16.row.col.f32.f16.f16.f32 "
        "{%0,%1,%2,%3}, {%4,%5,%6,%7}, {%8,%9}, {%0,%1,%2,%3};"
        : "+f"(c[0]), "+f"(c[1]), "+f"(c[2]), "+f"(c[3])
        : "r"(a[0]), "r"(a[1]), "r"(a[2]), "r"(a[3]), "r"(b[0]), "r"(b[1]));
}

__device__ __forceinline__ void ldsm_x4(uint32_t& r0, uint32_t& r1,
                                        uint32_t& r2, uint32_t& r3,
                                        uint32_t addr) {
    asm volatile(
        "ldmatrix.sync.aligned.m8n8.x4.shared.b16 {%0,%1,%2,%3}, [%4];"
        : "=r"(r0), "=r"(r1), "=r"(r2), "=r"(r3) : "r"(addr));
}

__device__ __forceinline__ void cpa16(uint32_t smem_addr, const void* gptr) {
    asm volatile("cp.async.cg.shared.global [%0], [%1], 16;"
                 :: "r"(smem_addr), "l"(gptr));
}
__device__ __forceinline__ void cpa_commit() {
    asm volatile("cp.async.commit_group;");
}
template <int N>
__device__ __forceinline__ void cpa_wait() {
    asm volatile("cp.async.wait_group %0;" :: "n"(N));
}

__device__ __forceinline__ float ex2(float x) {
    float r;
    asm("ex2.approx.ftz.f32 %0, %1;" : "=f"(r) : "f"(x));
    return r;
}

// ---------------------------------------------------------------------------
// Pre-passes
// ---------------------------------------------------------------------------
__global__ void convert_half_kernel(const float* __restrict__ in,
                                    __half* __restrict__ out, int n)
{
    int i = (blockIdx.x * blockDim.x + threadIdx.x) * 4;
    if (i >= n) return;
    float4 v = *(const float4*)&in[i];
    __half2 h0 = __floats2half2_rn(v.x, v.y);
    __half2 h1 = __floats2half2_rn(v.z, v.w);
    *(uint2*)&out[i] = make_uint2(*(uint32_t*)&h0, *(uint32_t*)&h1);
}

__global__ void transpose_half_kernel(const float* __restrict__ in,
                                      __half* __restrict__ out, int R, int C)
{
    __shared__ float tile[32][33];
    int c0 = blockIdx.x * 32, r0 = blockIdx.y * 32;
    int tx = threadIdx.x, ty = threadIdx.y;
    #pragma unroll
    for (int j = 0; j < 32; j += 8)
        tile[ty + j][tx] = in[(size_t)(r0 + ty + j) * C + c0 + tx];
    __syncthreads();
    #pragma unroll
    for (int j = 0; j < 32; j += 8)
        out[(size_t)(c0 + ty + j) * R + r0 + tx] = __float2half(tile[tx][ty + j]);
}

__global__ void transpose_h2h_kernel(const __half* __restrict__ in,
                                     __half* __restrict__ out, int R, int C)
{
    __shared__ __half tile[32][34];
    int c0 = blockIdx.x * 32, r0 = blockIdx.y * 32;
    int tx = threadIdx.x, ty = threadIdx.y;
    #pragma unroll
    for (int j = 0; j < 32; j += 8)
        tile[ty + j][tx] = in[(size_t)(r0 + ty + j) * C + c0 + tx];
    __syncthreads();
    #pragma unroll
    for (int j = 0; j < 32; j += 8)
        out[(size_t)(c0 + ty + j) * R + r0 + tx] = tile[tx][ty + j];
}

// ---------------------------------------------------------------------------
// FP16 GEMM, CTA tile 256x128 (MxN), 256 threads, 8 warps (4m x 2n),
// warp tile 64x64, K-chunk 64, cp.async 2-stage, ldmatrix frags.
// MODE 0: C32 = A @ BT^T (fp32 out)                         [O projection]
// MODE 3: merged QKV, N=6144 (Q rope*mul | K rope | V fp16)
// ---------------------------------------------------------------------------
#define GBM 256
#define GBN 128
#define GKC 64
#define A_WORDS_G (256 * 36)     // 9216
#define B_WORDS_G (128 * 36)     // 4608
#define STAGE_W (A_WORDS_G + B_WORDS_G)   // 13824
#define GEMM_SMEM_W (2 * STAGE_W)         // 27648 w = 110592 B

template <int MODE>
__global__ __launch_bounds__(256, 1) void gemm_epi_kernel(
    const __half* __restrict__ A, const __half* __restrict__ BT,
    float* __restrict__ C32, __half* __restrict__ Qo,
    __half* __restrict__ Ko, __half* __restrict__ Vo,
    const float* __restrict__ cs, const float* __restrict__ sn,
    int M, int N, int K, float mul)
{
    extern __shared__ uint32_t smg[];
    uint32_t sbase = (uint32_t)__cvta_generic_to_shared(smg);

    int tid = threadIdx.x;
    int wid = tid >> 5, lane = tid & 31;
    int g = lane >> 2, tg = lane & 3;
    int warp_m = (wid >> 1) * 64;     // 0,64,128,192
    int warp_n = (wid & 1) * 64;      // 0,64
    int m0 = blockIdx.y * GBM, n0 = blockIdx.x * GBN;

    uint32_t a_lane = (uint32_t)(lane & 15) * 144 + (uint32_t)(lane >> 4) * 16;
    uint32_t b_lane = ((uint32_t)((lane & 7) + ((lane >> 4) & 1) * 8)) * 144
                    + (uint32_t)((lane >> 3) & 1) * 16;

    float acc[4][8][4];
    #pragma unroll
    for (int mt = 0; mt < 4; mt++)
        #pragma unroll
        for (int nt = 0; nt < 8; nt++)
            #pragma unroll
            for (int i = 0; i < 4; i++) acc[mt][nt][i] = 0.f;

    int niter = K / GKC;

    // A: 256 rows x 8 granules = 2048 (8/thread); B: 128 x 8 = 1024 (4/thread)
    #define ISSUE_COPY(IT, STG)                                               \
    do {                                                                      \
        uint32_t aOff = sbase + (uint32_t)(STG) * STAGE_W * 4;                \
        uint32_t bOff = aOff + A_WORDS_G * 4;                                 \
        const __half* Ab = A + (size_t)m0 * K + (IT) * GKC;                   \
        const __half* Bb = BT + (size_t)n0 * K + (IT) * GKC;                  \
        _Pragma("unroll")                                                     \
        for (int i = 0; i < 8; i++) {                                         \
            int c = tid + i * 256;                                            \
            int r = c >> 3, cc = c & 7;                                       \
            cpa16(aOff + r * 144 + cc * 16, Ab + (size_t)r * K + cc * 8);     \
        }                                                                     \
        _Pragma("unroll")                                                     \
        for (int i = 0; i < 4; i++) {                                         \
            int c = tid + i * 256;                                            \
            int r = c >> 3, cc = c & 7;                                       \
            cpa16(bOff + r * 144 + cc * 16, Bb + (size_t)r * K + cc * 8);     \
        }                                                                     \
        cpa_commit();                                                         \
    } while (0)

    ISSUE_COPY(0, 0);

    for (int it = 0; it < niter; it++) {
        int cur = it & 1;
        if (it + 1 < niter) {
            ISSUE_COPY(it + 1, (it + 1) & 1);
            cpa_wait<1>();
        } else {
            cpa_wait<0>();
        }
        __syncthreads();

        uint32_t As_sh = sbase + (uint32_t)cur * STAGE_W * 4;
        uint32_t Bs_sh = As_sh + A_WORDS_G * 4;

        #pragma unroll
        for (int ks = 0; ks < 4; ks++) {
            uint32_t aR[4][4];
            #pragma unroll
            for (int mt = 0; mt < 4; mt++)
                ldsm_x4(aR[mt][0], aR[mt][1], aR[mt][2], aR[mt][3],
                        As_sh + (warp_m + mt * 16) * 144 + ks * 32 + a_lane);
            uint32_t bR[8][2];
            #pragma unroll
            for (int p = 0; p < 4; p++)
                ldsm_x4(bR[2 * p][0], bR[2 * p][1],
                        bR[2 * p + 1][0], bR[2 * p + 1][1],
                        Bs_sh + (warp_n + 16 * p) * 144 + ks * 32 + b_lane);
            #pragma unroll
            for (int mt = 0; mt < 4; mt++)
                #pragma unroll
                for (int nt = 0; nt < 8; nt++)
                    mma_f16(acc[mt][nt], aR[mt], bR[nt]);
        }
        __syncthreads();
    }

    if (MODE == 0) {
        #pragma unroll
        for (int mt = 0; mt < 4; mt++) {
            int m = m0 + warp_m + mt * 16 + g;
            #pragma unroll
            for (int nt = 0; nt < 8; nt++) {
                int n = n0 + warp_n + nt * 8 + 2 * tg;
                *(float2*)&C32[(size_t)m * N + n] =
                    make_float2(acc[mt][nt][0], acc[mt][nt][1]);
                *(float2*)&C32[(size_t)(m + 8) * N + n] =
                    make_float2(acc[mt][nt][2], acc[mt][nt][3]);
            }
        }
    } else {
        int sel = (n0 < DIM) ? 0 : ((n0 < DIM + KVDIM) ? 1 : 2);
        __half* outp = (sel == 0) ? Qo : ((sel == 1) ? Ko : Vo);
        int ld = (sel == 0) ? DIM : KVDIM;
        int nbase = (sel == 0) ? 0 : ((sel == 1) ? DIM : DIM + KVDIM);
        float mm = (sel == 0) ? mul : 1.0f;
        #pragma unroll
        for (int mt = 0; mt < 4; mt++) {
            int m = m0 + warp_m + mt * 16 + g;
            #pragma unroll
            for (int nt = 0; nt < 8; nt++) {
                int n = n0 + warp_n + nt * 8 + 2 * tg;
                int nc = n - nbase;
                if (sel == 2) {
                    __half2 h0 = __floats2half2_rn(acc[mt][nt][0], acc[mt][nt][1]);
                    __half2 h1 = __floats2half2_rn(acc[mt][nt][2], acc[mt][nt][3]);
                    *(uint32_t*)&outp[(size_t)m * ld + nc] = *(uint32_t*)&h0;
                    *(uint32_t*)&outp[(size_t)(m + 8) * ld + nc] = *(uint32_t*)&h1;
                } else {
                    int i = (nc & 127) >> 1;
                    float c0v = cs[m * 64 + i],       s0v = sn[m * 64 + i];
                    float c1v = cs[(m + 8) * 64 + i], s1v = sn[(m + 8) * 64 + i];
                    float re0 = acc[mt][nt][0] * c0v - acc[mt][nt][1] * s0v;
                    float im0 = acc[mt][nt][0] * s0v + acc[mt][nt][1] * c0v;
                    float re1 = acc[mt][nt][2] * c1v - acc[mt][nt][3] * s1v;
                    float im1 = acc[mt][nt][2] * s1v + acc[mt][nt][3] * c1v;
                    __half2 h0 = __floats2half2_rn(re0 * mm, im0 * mm);
                    __half2 h1 = __floats2half2_rn(re1 * mm, im1 * mm);
                    *(uint32_t*)&outp[(size_t)m * ld + nc] = *(uint32_t*)&h0;
                    *(uint32_t*)&outp[(size_t)(m + 8) * ld + nc] = *(uint32_t*)&h1;
                }
            }
        }
    }
}

// ---------------------------------------------------------------------------
// Flash attention, all-fp16, cp.async-pipelined K/V, base-2 softmax.
// smem (words): P 2304 | K0 4352 | K1 4352 | V 4608  = 15616 w.
// ---------------------------------------------------------------------------
#define FBR 64
#define QKSTR 68
#define P16STR 36
#define VSTR 36
#define P_OFF 0
#define K_OFF0 2304
#define K_OFF1 6656
#define V_OFF 11008
#define FLASH_SMEM_W 15616

__global__ __launch_bounds__(128, 3) void flash_kernel(
    const __half* __restrict__ Q16, const __half* __restrict__ K16,
    const __half* __restrict__ Vt, __half* __restrict__ O)
{
    extern __shared__ uint32_t smu[];
    uint32_t* Ps16 = smu + P_OFF;
    uint32_t* Qh   = smu + K_OFF0;
    uint32_t sm_sh  = (uint32_t)__cvta_generic_to_shared(smu);
    uint32_t Ps_sh  = sm_sh + P_OFF * 4;
    uint32_t K_sh[2] = { sm_sh + K_OFF0 * 4, sm_sh + K_OFF1 * 4 };
    uint32_t V_sh   = sm_sh + V_OFF * 4;

    int tid = threadIdx.x;
    int w = tid >> 5, lane = tid & 31;
    int g = lane >> 2, tg = lane & 3;
    int h = blockIdx.y, kvh = h >> 2;
    int diag = (int)gridDim.x - 1 - (int)blockIdx.x;
    int r0 = diag * FBR;

    uint32_t kb_lane = ((uint32_t)((lane & 7) + ((lane >> 4) & 1) * 8)) * 272
                     + (uint32_t)((lane >> 3) & 1) * 16;
    uint32_t pa_lane = (uint32_t)(lane & 15) * 144
                     + (uint32_t)(lane >> 4) * 16;
    uint32_t vb_lane = ((uint32_t)((lane & 7) + ((lane >> 4) & 1) * 8)) * 144
                     + (uint32_t)((lane >> 3) & 1) * 16;

    for (int t = tid; t < FBR * 16; t += 128) {
        int row = t >> 4, c = t & 15;
        *(uint4*)&Qh[row * QKSTR + c * 4] =
            *(const uint4*)&Q16[(size_t)(r0 + row) * DIM + h * HD + c * 8];
    }
    __syncthreads();

    uint32_t qa[8][4];
    {
        int mrow = (16 * w + g) * QKSTR;
        #pragma unroll
        for (int ks = 0; ks < 8; ks++) {
            int k0 = ks * 8;
            qa[ks][0] = Qh[mrow + k0 + tg];
            qa[ks][1] = Qh[mrow + 8 * QKSTR + k0 + tg];
            qa[ks][2] = Qh[mrow + k0 + tg + 4];
            qa[ks][3] = Qh[mrow + 8 * QKSTR + k0 + tg + 4];
        }
    }
    __syncthreads();

    #define ISSUE_K(KT, KSH)                                                  \
    do {                                                                      \
        const __half* Kb = K16 + (size_t)((KT) * FBR) * KVDIM + kvh * HD;     \
        _Pragma("unroll")                                                     \
        for (int i = 0; i < 8; i++) {                                         \
            int c = tid + i * 128;                                            \
            int r = c >> 4, cc = c & 15;                                      \
            cpa16((KSH) + r * 272 + cc * 16, Kb + (size_t)r * KVDIM + cc * 8);\
        }                                                                     \
        cpa_commit();                                                         \
    } while (0)

    #define ISSUE_V(KT)                                                      \
    do {                                                                     \
        const __half* Vb = Vt + (size_t)(kvh * HD) * SEQ + (KT) * FBR;       \
        _Pragma("unroll")                                                    \
        for (int i = 0; i < 8; i++) {                                        \
            int c = tid + i * 128;                                           \
            int r = c >> 3, cc = c & 7;                                      \
            cpa16(V_sh + r * 144 + cc * 16, Vb + (size_t)r * SEQ + cc * 8);  \
        }                                                                    \
        cpa_commit();                                                        \
    } while (0)

    float m0 = -1e30f, m1 = -1e30f, l0 = 0.f, l1 = 0.f;
    float o[16][4];
    #pragma unroll
    for (int nt = 0; nt < 16; nt++)
        #pragma unroll
        for (int i = 0; i < 4; i++) o[nt][i] = 0.f;

    int qrow_g = r0 + 16 * w + g;

    ISSUE_K(0, K_sh[0]);

    for (int kt = 0; kt <= diag; kt++) {
        int c0 = kt * FBR;
        int cur = kt & 1;
        uint32_t Kh_sh = K_sh[cur];

        cpa_wait<0>();
        __syncthreads();

        ISSUE_V(kt);
        if (kt < diag) ISSUE_K(kt + 1, K_sh[cur ^ 1]);

        // ---- S = Q @ K^T (scores in base-2 domain) ----
        float sacc[8][4];
        #pragma unroll
        for (int nt = 0; nt < 8; nt++)
            #pragma unroll
            for (int i = 0; i < 4; i++) sacc[nt][i] = 0.f;

        #pragma unroll
        for (int ks = 0; ks < 8; ks++) {
            #pragma unroll
            for (int p = 0; p < 4; p++) {
                uint32_t b0, b1, b2, b3;
                ldsm_x4(b0, b1, b2, b3,
                        Kh_sh + (16 * p) * 272 + ks * 32 + kb_lane);
                uint32_t bb0[2] = { b0, b1 };
                uint32_t bb1[2] = { b2, b3 };
                mma_f16(sacc[2 * p], qa[ks], bb0);
                mma_f16(sacc[2 * p + 1], qa[ks], bb1);
            }
        }

        if (kt == diag) {
            #pragma unroll
            for (int nt = 0; nt < 8; nt++) {
                int col = c0 + 8 * nt + 2 * tg;
                if (col > qrow_g)          sacc[nt][0] = -1e30f;
                if (col + 1 > qrow_g)      sacc[nt][1] = -1e30f;
                if (col > qrow_g + 8)      sacc[nt][2] = -1e30f;
                if (col + 1 > qrow_g + 8)  sacc[nt][3] = -1e30f;
            }
        }

        // ---- online softmax (base 2) ----
        float mx0 = -1e30f, mx1 = -1e30f;
        #pragma unroll
        for (int nt = 0; nt < 8; nt++) {
            mx0 = fmaxf(mx0, fmaxf(sacc[nt][0], sacc[nt][1]));
            mx1 = fmaxf(mx1, fmaxf(sacc[nt][2], sacc[nt][3]));
        }
        #pragma unroll
        for (int off = 2; off >= 1; off >>= 1) {
            mx0 = fmaxf(mx0, __shfl_xor_sync(0xffffffffu, mx0, off));
            mx1 = fmaxf(mx1, __shfl_xor_sync(0xffffffffu, mx1, off));
        }
        float mn0 = fmaxf(m0, mx0), mn1 = fmaxf(m1, mx1);
        float cor0 = ex2(m0 - mn0), cor1 = ex2(m1 - mn1);
        float ps0 = 0.f, ps1 = 0.f;
        #pragma unroll
        for (int nt = 0; nt < 8; nt++) {
            sacc[nt][0] = ex2(sacc[nt][0] - mn0);
            sacc[nt][1] = ex2(sacc[nt][1] - mn0);
            sacc[nt][2] = ex2(sacc[nt][2] - mn1);
            sacc[nt][3] = ex2(sacc[nt][3] - mn1);
            ps0 += sacc[nt][0] + sacc[nt][1];
            ps1 += sacc[nt][2] + sacc[nt][3];
        }
        #pragma unroll
        for (int off = 2; off >= 1; off >>= 1) {
            ps0 += __shfl_xor_sync(0xffffffffu, ps0, off);
            ps1 += __shfl_xor_sync(0xffffffffu, ps1, off);
        }
        l0 = l0 * cor0 + ps0;  m0 = mn0;
        l1 = l1 * cor1 + ps1;  m1 = mn1;
        // skip O-rescale when the max didn't move anywhere in this warp
        bool noresc = __all_sync(0xffffffffu,
                                 (cor0 == 1.0f) && (cor1 == 1.0f));
        if (!noresc) {
            #pragma unroll
            for (int nt = 0; nt < 16; nt++) {
                o[nt][0] *= cor0; o[nt][1] *= cor0;
                o[nt][2] *= cor1; o[nt][3] *= cor1;
            }
        }
        #pragma unroll
        for (int nt = 0; nt < 8; nt++) {
            __half2 p0 = __floats2half2_rn(sacc[nt][0], sacc[nt][1]);
            __half2 p1 = __floats2half2_rn(sacc[nt][2], sacc[nt][3]);
            Ps16[(16 * w + g) * P16STR + nt * 4 + tg] = *(uint32_t*)&p0;
            Ps16[(16 * w + g + 8) * P16STR + nt * 4 + tg] = *(uint32_t*)&p1;
        }

        if (kt < diag) cpa_wait<1>(); else cpa_wait<0>();
        __syncthreads();

        // ---- O += P @ V ----
        #pragma unroll
        for (int ks = 0; ks < 4; ks++) {
            uint32_t a[4];
            ldsm_x4(a[0], a[1], a[2], a[3],
                    Ps_sh + (16 * w) * 144 + ks * 32 + pa_lane);
            #pragma unroll
            for (int p = 0; p < 8; p++) {
                uint32_t b0, b1, b2, b3;
                ldsm_x4(b0, b1, b2, b3,
                        V_sh + (16 * p) * 144 + ks * 32 + vb_lane);
                uint32_t bb0[2] = { b0, b1 };
                uint32_t bb1[2] = { b2, b3 };
                mma_f16(o[2 * p], a, bb0);
                mma_f16(o[2 * p + 1], a, bb1);
            }
        }
    }

    float i0 = 1.f / l0, i1 = 1.f / l1;
    #pragma unroll
    for (int nt = 0; nt < 16; nt++) {
        int col = h * HD + 8 * nt + 2 * tg;
        __half2 h0 = __floats2half2_rn(o[nt][0] * i0, o[nt][1] * i0);
        __half2 h1 = __floats2half2_rn(o[nt][2] * i1, o[nt][3] * i1);
        *(uint32_t*)&O[(size_t)qrow_g * DIM + col] = *(uint32_t*)&h0;
        *(uint32_t*)&O[(size_t)(qrow_g + 8) * DIM + col] = *(uint32_t*)&h1;
    }
}

// ---------------------------------------------------------------------------
// Launch
// ---------------------------------------------------------------------------
extern "C" void kernel_launch(void* const* d_in, const int* in_sizes, int n_in,
                              void* d_out, int out_size)
{
    const float* x  = (const float*)d_in[0];
    const float* wq = (const float*)d_in[1];
    const float* wk = (const float*)d_in[2];
    const float* wv = (const float*)d_in[3];
    const float* wo = (const float*)d_in[4];
    const float* fc = (const float*)d_in[5];
    const float* fs = (const float*)d_in[6];

    __half *Q16, *K16, *V16, *VT, *A16, *X16, *WqkvT, *WoT;
    cudaGetSymbolAddress((void**)&Q16, g_Q16);
    cudaGetSymbolAddress((void**)&K16, g_K16);
    cudaGetSymbolAddress((void**)&V16, g_V16);
    cudaGetSymbolAddress((void**)&VT, g_vT);
    cudaGetSymbolAddress((void**)&A16, g_attn16);
    cudaGetSymbolAddress((void**)&X16, g_x16);
    cudaGetSymbolAddress((void**)&WqkvT, g_wqkvT);
    cudaGetSymbolAddress((void**)&WoT, g_woT);

    // Pre-passes
    convert_half_kernel<<<SEQ * DIM / 4 / 256, 256>>>(x, X16, SEQ * DIM);
    dim3 tb(32, 8);
    transpose_half_kernel<<<dim3(DIM / 32, DIM / 32), tb>>>(wq, WqkvT, DIM, DIM);
    transpose_half_kernel<<<dim3(KVDIM / 32, DIM / 32), tb>>>(
        wk, WqkvT + (size_t)DIM * DIM, DIM, KVDIM);
    transpose_half_kernel<<<dim3(KVDIM / 32, DIM / 32), tb>>>(
        wv, WqkvT + (size_t)(DIM + KVDIM) * DIM, DIM, KVDIM);
    transpose_half_kernel<<<dim3(DIM / 32, DIM / 32), tb>>>(wo, WoT, DIM, DIM);

    int gsm = GEMM_SMEM_W * (int)sizeof(uint32_t);
    cudaFuncSetAttribute(gemm_epi_kernel<0>,
                         cudaFuncAttributeMaxDynamicSharedMemorySize, gsm);
    cudaFuncSetAttribute(gemm_epi_kernel<3>,
                         cudaFuncAttributeMaxDynamicSharedMemorySize, gsm);

    // Q scale folds 1/sqrt(128) and log2(e) (base-2 softmax domain)
    const float qscale = 0.08838834764831845f * 1.4426950408889634f;

    // Fused Q|K|V projection: 48 x 8 = 384 CTAs of 256 threads.
    gemm_epi_kernel<3><<<dim3(NQKV / GBN, SEQ / GBM), 256, gsm>>>(
        X16, WqkvT, nullptr, Q16, K16, V16, fc, fs, SEQ, NQKV, DIM, qscale);

    // V -> V^T (fp16)
    transpose_h2h_kernel<<<dim3(KVDIM / 32, SEQ / 32), tb>>>(V16, VT, SEQ, KVDIM);

    // Flash attention (pipelined, base-2 softmax) -> fp16 attn
    int fsm = FLASH_SMEM_W * (int)sizeof(uint32_t);
    cudaFuncSetAttribute(flash_kernel,
                         cudaFuncAttributeMaxDynamicSharedMemorySize, fsm);
    flash_kernel<<<dim3(SEQ / FBR, NH), 128, fsm>>>(Q16, K16, VT, A16);

    // Output projection -> d_out (fp32): 32 x 8 CTAs
    gemm_epi_kernel<0><<<dim3(DIM / GBN, SEQ / GBM), 256, gsm>>>(
        A16, WoT, (float*)d_out, nullptr, nullptr, nullptr, nullptr, nullptr,
        SEQ, DIM, DIM, 1.0f);
}

// round 16
// speedup vs baseline: 1.1347x; 1.1347x over previous
#include <cuda_runtime.h>
#include <cuda_fp16.h>
#include <math.h>
#include <stdint.h>

#define SEQ 2048
#define DIM 4096
#define NH 32
#define NKV 8
#define HD 128
#define KVDIM 1024
#define NQKV (DIM + 2 * KVDIM)    // 6144 fused projection width

// Scratch (allocation-free rule: device globals)
__device__ __half g_Q16[SEQ * DIM];         // roped+scaled Q (base-2 domain)
__device__ __half g_K16[SEQ * KVDIM];       // roped K, fp16
__device__ __half g_V16[SEQ * KVDIM];       // V, fp16
__device__ __half g_vT[KVDIM * SEQ];        // V^T fp16 [KVDIM][SEQ]
__device__ __half g_attn16[SEQ * DIM];      // flash output, fp16
__device__ __half g_x16[SEQ * DIM];         // x, fp16
__device__ __half g_wqkvT[NQKV * DIM];      // [Wq^T; Wk^T; Wv^T] fp16
__device__ __half g_woT[DIM * DIM];

// ---------------------------------------------------------------------------
// Helpers
// ---------------------------------------------------------------------------
__device__ __forceinline__ void mma_f16(float c[4], const uint32_t a[4],
                                        const uint32_t b[2]) {
    asm volatile(
        "mma.sync.aligned.m16n8k16.row.col.f32.f16.f16.f32 "
        "{%0,%1,%2,%3}, {%4,%5,%6,%7}, {%8,%9}, {%0,%1,%2,%3};"
        : "+f"(c[0]), "+f"(c[1]), "+f"(c[2]), "+f"(c[3])
        : "r"(a[0]), "r"(a[1]), "r"(a[2]), "r"(a[3]), "r"(b[0]), "r"(b[1]));
}

__device__ __forceinline__ void ldsm_x4(uint32_t& r0, uint32_t& r1,
                                        uint32_t& r2, uint32_t& r3,
                                        uint32_t addr) {
    asm volatile(
        "ldmatrix.sync.aligned.m8n8.x4.shared.b16 {%0,%1,%2,%3}, [%4];"
        : "=r"(r0), "=r"(r1), "=r"(r2), "=r"(r3) : "r"(addr));
}

__device__ __forceinline__ void cpa16(uint32_t smem_addr, const void* gptr) {
    asm volatile("cp.async.cg.shared.global [%0], [%1], 16;"
                 :: "r"(smem_addr), "l"(gptr));
}
__device__ __forceinline__ void cpa_commit() {
    asm volatile("cp.async.commit_group;");
}
template <int N>
__device__ __forceinline__ void cpa_wait() {
    asm volatile("cp.async.wait_group %0;" :: "n"(N));
}

__device__ __forceinline__ float ex2(float x) {
    float r;
    asm("ex2.approx.ftz.f32 %0, %1;" : "=f"(r) : "f"(x));
    return r;
}

// ---------------------------------------------------------------------------
// Pre-passes
// ---------------------------------------------------------------------------
__global__ void convert_half_kernel(const float* __restrict__ in,
                                    __half* __restrict__ out, int n)
{
    int i = (blockIdx.x * blockDim.x + threadIdx.x) * 4;
    if (i >= n) return;
    float4 v = *(const float4*)&in[i];
    __half2 h0 = __floats2half2_rn(v.x, v.y);
    __half2 h1 = __floats2half2_rn(v.z, v.w);
    *(uint2*)&out[i] = make_uint2(*(uint32_t*)&h0, *(uint32_t*)&h1);
}

__global__ void transpose_half_kernel(const float* __restrict__ in,
                                      __half* __restrict__ out, int R, int C)
{
    __shared__ float tile[32][33];
    int c0 = blockIdx.x * 32, r0 = blockIdx.y * 32;
    int tx = threadIdx.x, ty = threadIdx.y;
    #pragma unroll
    for (int j = 0; j < 32; j += 8)
        tile[ty + j][tx] = in[(size_t)(r0 + ty + j) * C + c0 + tx];
    __syncthreads();
    #pragma unroll
    for (int j = 0; j < 32; j += 8)
        out[(size_t)(c0 + ty + j) * R + r0 + tx] = __float2half(tile[tx][ty + j]);
}

__global__ void transpose_h2h_kernel(const __half* __restrict__ in,
                                     __half* __restrict__ out, int R, int C)
{
    __shared__ __half tile[32][34];
    int c0 = blockIdx.x * 32, r0 = blockIdx.y * 32;
    int tx = threadIdx.x, ty = threadIdx.y;
    #pragma unroll
    for (int j = 0; j < 32; j += 8)
        tile[ty + j][tx] = in[(size_t)(r0 + ty + j) * C + c0 + tx];
    __syncthreads();
    #pragma unroll
    for (int j = 0; j < 32; j += 8)
        out[(size_t)(c0 + ty + j) * R + r0 + tx] = tile[tx][ty + j];
}

// ---------------------------------------------------------------------------
// FP16 GEMM with fused epilogues — round-14 config (128x128, 128 thr, occ 2).
// MODE 0: C32 = A @ BT^T (fp32 out)                         [O projection]
// MODE 3: merged QKV, N=6144 (Q rope*mul | K rope | V fp16)
// ---------------------------------------------------------------------------
#define GBM 128
#define GBN 128
#define GKC 64
#define HSTR 36
#define TILE_WORDS (128 * HSTR)

template <int MODE>
__global__ __launch_bounds__(128, 2) void gemm_epi_kernel(
    const __half* __restrict__ A, const __half* __restrict__ BT,
    float* __restrict__ C32, __half* __restrict__ Qo,
    __half* __restrict__ Ko, __half* __restrict__ Vo,
    const float* __restrict__ cs, const float* __restrict__ sn,
    int M, int N, int K, float mul)
{
    extern __shared__ uint32_t smg[];
    uint32_t sbase = (uint32_t)__cvta_generic_to_shared(smg);

    int tid = threadIdx.x;
    int wid = tid >> 5, lane = tid & 31;
    int g = lane >> 2, tg = lane & 3;
    int warp_m = (wid >> 1) * 64;
    int warp_n = (wid & 1) * 64;
    int m0 = blockIdx.y * GBM, n0 = blockIdx.x * GBN;

    uint32_t a_lane = (uint32_t)(lane & 15) * 144 + (uint32_t)(lane >> 4) * 16;
    uint32_t b_lane = ((uint32_t)((lane & 7) + ((lane >> 4) & 1) * 8)) * 144
                    + (uint32_t)((lane >> 3) & 1) * 16;

    float acc[4][8][4];
    #pragma unroll
    for (int mt = 0; mt < 4; mt++)
        #pragma unroll
        for (int nt = 0; nt < 8; nt++)
            #pragma unroll
            for (int i = 0; i < 4; i++) acc[mt][nt][i] = 0.f;

    int niter = K / GKC;

    #define ISSUE_COPY(IT, STG)                                               \
    do {                                                                      \
        uint32_t aOff = sbase + (uint32_t)(STG) * (2 * TILE_WORDS) * 4;       \
        uint32_t bOff = aOff + TILE_WORDS * 4;                                \
        const __half* Ab = A + (size_t)m0 * K + (IT) * GKC;                   \
        const __half* Bb = BT + (size_t)n0 * K + (IT) * GKC;                  \
        _Pragma("unroll")                                                     \
        for (int i = 0; i < 8; i++) {                                         \
            int c = tid + i * 128;                                            \
            int r = c >> 3, cc = c & 7;                                       \
            cpa16(aOff + r * 144 + cc * 16, Ab + (size_t)r * K + cc * 8);     \
        }                                                                     \
        _Pragma("unroll")                                                     \
        for (int i = 0; i < 8; i++) {                                         \
            int c = tid + i * 128;                                            \
            int r = c >> 3, cc = c & 7;                                       \
            cpa16(bOff + r * 144 + cc * 16, Bb + (size_t)r * K + cc * 8);     \
        }                                                                     \
        cpa_commit();                                                         \
    } while (0)

    ISSUE_COPY(0, 0);

    for (int it = 0; it < niter; it++) {
        int cur = it & 1;
        if (it + 1 < niter) {
            ISSUE_COPY(it + 1, (it + 1) & 1);
            cpa_wait<1>();
        } else {
            cpa_wait<0>();
        }
        __syncthreads();

        uint32_t As_sh = sbase + (uint32_t)cur * (2 * TILE_WORDS) * 4;
        uint32_t Bs_sh = As_sh + TILE_WORDS * 4;

        #pragma unroll
        for (int ks = 0; ks < 4; ks++) {
            uint32_t aR[4][4];
            #pragma unroll
            for (int mt = 0; mt < 4; mt++)
                ldsm_x4(aR[mt][0], aR[mt][1], aR[mt][2], aR[mt][3],
                        As_sh + (warp_m + mt * 16) * 144 + ks * 32 + a_lane);
            uint32_t bR[8][2];
            #pragma unroll
            for (int p = 0; p < 4; p++)
                ldsm_x4(bR[2 * p][0], bR[2 * p][1],
                        bR[2 * p + 1][0], bR[2 * p + 1][1],
                        Bs_sh + (warp_n + 16 * p) * 144 + ks * 32 + b_lane);
            #pragma unroll
            for (int mt = 0; mt < 4; mt++)
                #pragma unroll
                for (int nt = 0; nt < 8; nt++)
                    mma_f16(acc[mt][nt], aR[mt], bR[nt]);
        }
        __syncthreads();
    }

    if (MODE == 0) {
        #pragma unroll
        for (int mt = 0; mt < 4; mt++) {
            int m = m0 + warp_m + mt * 16 + g;
            #pragma unroll
            for (int nt = 0; nt < 8; nt++) {
                int n = n0 + warp_n + nt * 8 + 2 * tg;
                *(float2*)&C32[(size_t)m * N + n] =
                    make_float2(acc[mt][nt][0], acc[mt][nt][1]);
                *(float2*)&C32[(size_t)(m + 8) * N + n] =
                    make_float2(acc[mt][nt][2], acc[mt][nt][3]);
            }
        }
    } else {
        int sel = (n0 < DIM) ? 0 : ((n0 < DIM + KVDIM) ? 1 : 2);
        __half* outp = (sel == 0) ? Qo : ((sel == 1) ? Ko : Vo);
        int ld = (sel == 0) ? DIM : KVDIM;
        int nbase = (sel == 0) ? 0 : ((sel == 1) ? DIM : DIM + KVDIM);
        float mm = (sel == 0) ? mul : 1.0f;
        #pragma unroll
        for (int mt = 0; mt < 4; mt++) {
            int m = m0 + warp_m + mt * 16 + g;
            #pragma unroll
            for (int nt = 0; nt < 8; nt++) {
                int n = n0 + warp_n + nt * 8 + 2 * tg;
                int nc = n - nbase;
                if (sel == 2) {
                    __half2 h0 = __floats2half2_rn(acc[mt][nt][0], acc[mt][nt][1]);
                    __half2 h1 = __floats2half2_rn(acc[mt][nt][2], acc[mt][nt][3]);
                    *(uint32_t*)&outp[(size_t)m * ld + nc] = *(uint32_t*)&h0;
                    *(uint32_t*)&outp[(size_t)(m + 8) * ld + nc] = *(uint32_t*)&h1;
                } else {
                    int i = (nc & 127) >> 1;
                    float c0v = cs[m * 64 + i],       s0v = sn[m * 64 + i];
                    float c1v = cs[(m + 8) * 64 + i], s1v = sn[(m + 8) * 64 + i];
                    float re0 = acc[mt][nt][0] * c0v - acc[mt][nt][1] * s0v;
                    float im0 = acc[mt][nt][0] * s0v + acc[mt][nt][1] * c0v;
                    float re1 = acc[mt][nt][2] * c1v - acc[mt][nt][3] * s1v;
                    float im1 = acc[mt][nt][2] * s1v + acc[mt][nt][3] * c1v;
                    __half2 h0 = __floats2half2_rn(re0 * mm, im0 * mm);
                    __half2 h1 = __floats2half2_rn(re1 * mm, im1 * mm);
                    *(uint32_t*)&outp[(size_t)m * ld + nc] = *(uint32_t*)&h0;
                    *(uint32_t*)&outp[(size_t)(m + 8) * ld + nc] = *(uint32_t*)&h1;
                }
            }
        }
    }
}

// ---------------------------------------------------------------------------
// Flash attention, all-fp16, cp.async-pipelined K/V, base-2 softmax,
// warp-uniform rescale skip. smem: P 2304 | K0 4352 | K1 4352 | V 4608.
// ---------------------------------------------------------------------------
#define FBR 64
#define QKSTR 68
#define P16STR 36
#define VSTR 36
#define P_OFF 0
#define K_OFF0 2304
#define K_OFF1 6656
#define V_OFF 11008
#define FLASH_SMEM_W 15616

__global__ __launch_bounds__(128, 3) void flash_kernel(
    const __half* __restrict__ Q16, const __half* __restrict__ K16,
    const __half* __restrict__ Vt, __half* __restrict__ O)
{
    extern __shared__ uint32_t smu[];
    uint32_t* Ps16 = smu + P_OFF;
    uint32_t* Qh   = smu + K_OFF0;
    uint32_t sm_sh  = (uint32_t)__cvta_generic_to_shared(smu);
    uint32_t Ps_sh  = sm_sh + P_OFF * 4;
    uint32_t K_sh[2] = { sm_sh + K_OFF0 * 4, sm_sh + K_OFF1 * 4 };
    uint32_t V_sh   = sm_sh + V_OFF * 4;

    int tid = threadIdx.x;
    int w = tid >> 5, lane = tid & 31;
    int g = lane >> 2, tg = lane & 3;
    int h = blockIdx.y, kvh = h >> 2;
    int diag = (int)gridDim.x - 1 - (int)blockIdx.x;
    int r0 = diag * FBR;

    uint32_t kb_lane = ((uint32_t)((lane & 7) + ((lane >> 4) & 1) * 8)) * 272
                     + (uint32_t)((lane >> 3) & 1) * 16;
    uint32_t pa_lane = (uint32_t)(lane & 15) * 144
                     + (uint32_t)(lane >> 4) * 16;
    uint32_t vb_lane = ((uint32_t)((lane & 7) + ((lane >> 4) & 1) * 8)) * 144
                     + (uint32_t)((lane >> 3) & 1) * 16;

    for (int t = tid; t < FBR * 16; t += 128) {
        int row = t >> 4, c = t & 15;
        *(uint4*)&Qh[row * QKSTR + c * 4] =
            *(const uint4*)&Q16[(size_t)(r0 + row) * DIM + h * HD + c * 8];
    }
    __syncthreads();

    uint32_t qa[8][4];
    {
        int mrow = (16 * w + g) * QKSTR;
        #pragma unroll
        for (int ks = 0; ks < 8; ks++) {
            int k0 = ks * 8;
            qa[ks][0] = Qh[mrow + k0 + tg];
            qa[ks][1] = Qh[mrow + 8 * QKSTR + k0 + tg];
            qa[ks][2] = Qh[mrow + k0 + tg + 4];
            qa[ks][3] = Qh[mrow + 8 * QKSTR + k0 + tg + 4];
        }
    }
    __syncthreads();

    #define ISSUE_K(KT, KSH)                                                  \
    do {                                                                      \
        const __half* Kb = K16 + (size_t)((KT) * FBR) * KVDIM + kvh * HD;     \
        _Pragma("unroll")                                                     \
        for (int i = 0; i < 8; i++) {                                         \
            int c = tid + i * 128;                                            \
            int r = c >> 4, cc = c & 15;                                      \
            cpa16((KSH) + r * 272 + cc * 16, Kb + (size_t)r * KVDIM + cc * 8);\
        }                                                                     \
        cpa_commit();                                                         \
    } while (0)

    #define ISSUE_V(KT)                                                      \
    do {                                                                     \
        const __half* Vb = Vt + (size_t)(kvh * HD) * SEQ + (KT) * FBR;       \
        _Pragma("unroll")                                                    \
        for (int i = 0; i < 8; i++) {                                        \
            int c = tid + i * 128;                                           \
            int r = c >> 3, cc = c & 7;                                      \
            cpa16(V_sh + r * 144 + cc * 16, Vb + (size_t)r * SEQ + cc * 8);  \
        }                                                                    \
        cpa_commit();                                                        \
    } while (0)

    float m0 = -1e30f, m1 = -1e30f, l0 = 0.f, l1 = 0.f;
    float o[16][4];
    #pragma unroll
    for (int nt = 0; nt < 16; nt++)
        #pragma unroll
        for (int i = 0; i < 4; i++) o[nt][i] = 0.f;

    int qrow_g = r0 + 16 * w + g;

    ISSUE_K(0, K_sh[0]);

    for (int kt = 0; kt <= diag; kt++) {
        int c0 = kt * FBR;
        int cur = kt & 1;
        uint32_t Kh_sh = K_sh[cur];

        cpa_wait<0>();
        __syncthreads();

        ISSUE_V(kt);
        if (kt < diag) ISSUE_K(kt + 1, K_sh[cur ^ 1]);

        // ---- S = Q @ K^T (scores in base-2 domain) ----
        float sacc[8][4];
        #pragma unroll
        for (int nt = 0; nt < 8; nt++)
            #pragma unroll
            for (int i = 0; i < 4; i++) sacc[nt][i] = 0.f;

        #pragma unroll
        for (int ks = 0; ks < 8; ks++) {
            #pragma unroll
            for (int p = 0; p < 4; p++) {
                uint32_t b0, b1, b2, b3;
                ldsm_x4(b0, b1, b2, b3,
                        Kh_sh + (16 * p) * 272 + ks * 32 + kb_lane);
                uint32_t bb0[2] = { b0, b1 };
                uint32_t bb1[2] = { b2, b3 };
                mma_f16(sacc[2 * p], qa[ks], bb0);
                mma_f16(sacc[2 * p + 1], qa[ks], bb1);
            }
        }

        if (kt == diag) {
            #pragma unroll
            for (int nt = 0; nt < 8; nt++) {
                int col = c0 + 8 * nt + 2 * tg;
                if (col > qrow_g)          sacc[nt][0] = -1e30f;
                if (col + 1 > qrow_g)      sacc[nt][1] = -1e30f;
                if (col > qrow_g + 8)      sacc[nt][2] = -1e30f;
                if (col + 1 > qrow_g + 8)  sacc[nt][3] = -1e30f;
            }
        }

        // ---- online softmax (base 2) ----
        float mx0 = -1e30f, mx1 = -1e30f;
        #pragma unroll
        for (int nt = 0; nt < 8; nt++) {
            mx0 = fmaxf(mx0, fmaxf(sacc[nt][0], sacc[nt][1]));
            mx1 = fmaxf(mx1, fmaxf(sacc[nt][2], sacc[nt][3]));
        }
        #pragma unroll
        for (int off = 2; off >= 1; off >>= 1) {
            mx0 = fmaxf(mx0, __shfl_xor_sync(0xffffffffu, mx0, off));
            mx1 = fmaxf(mx1, __shfl_xor_sync(0xffffffffu, mx1, off));
        }
        float mn0 = fmaxf(m0, mx0), mn1 = fmaxf(m1, mx1);
        float cor0 = ex2(m0 - mn0), cor1 = ex2(m1 - mn1);
        float ps0 = 0.f, ps1 = 0.f;
        #pragma unroll
        for (int nt = 0; nt < 8; nt++) {
            sacc[nt][0] = ex2(sacc[nt][0] - mn0);
            sacc[nt][1] = ex2(sacc[nt][1] - mn0);
            sacc[nt][2] = ex2(sacc[nt][2] - mn1);
            sacc[nt][3] = ex2(sacc[nt][3] - mn1);
            ps0 += sacc[nt][0] + sacc[nt][1];
            ps1 += sacc[nt][2] + sacc[nt][3];
        }
        #pragma unroll
        for (int off = 2; off >= 1; off >>= 1) {
            ps0 += __shfl_xor_sync(0xffffffffu, ps0, off);
            ps1 += __shfl_xor_sync(0xffffffffu, ps1, off);
        }
        l0 = l0 * cor0 + ps0;  m0 = mn0;
        l1 = l1 * cor1 + ps1;  m1 = mn1;
        bool noresc = __all_sync(0xffffffffu,
                                 (cor0 == 1.0f) && (cor1 == 1.0f));
        if (!noresc) {
            #pragma unroll
            for (int nt = 0; nt < 16; nt++) {
                o[nt][0] *= cor0; o[nt][1] *= cor0;
                o[nt][2] *= cor1; o[nt][3] *= cor1;
            }
        }
        #pragma unroll
        for (int nt = 0; nt < 8; nt++) {
            __half2 p0 = __floats2half2_rn(sacc[nt][0], sacc[nt][1]);
            __half2 p1 = __floats2half2_rn(sacc[nt][2], sacc[nt][3]);
            Ps16[(16 * w + g) * P16STR + nt * 4 + tg] = *(uint32_t*)&p0;
            Ps16[(16 * w + g + 8) * P16STR + nt * 4 + tg] = *(uint32_t*)&p1;
        }

        if (kt < diag) cpa_wait<1>(); else cpa_wait<0>();
        __syncthreads();

        // ---- O += P @ V ----
        #pragma unroll
        for (int ks = 0; ks < 4; ks++) {
            uint32_t a[4];
            ldsm_x4(a[0], a[1], a[2], a[3],
                    Ps_sh + (16 * w) * 144 + ks * 32 + pa_lane);
            #pragma unroll
            for (int p = 0; p < 8; p++) {
                uint32_t b0, b1, b2, b3;
                ldsm_x4(b0, b1, b2, b3,
                        V_sh + (16 * p) * 144 + ks * 32 + vb_lane);
                uint32_t bb0[2] = { b0, b1 };
                uint32_t bb1[2] = { b2, b3 };
                mma_f16(o[2 * p], a, bb0);
                mma_f16(o[2 * p + 1], a, bb1);
            }
        }
    }

    float i0 = 1.f / l0, i1 = 1.f / l1;
    #pragma unroll
    for (int nt = 0; nt < 16; nt++) {
        int col = h * HD + 8 * nt + 2 * tg;
        __half2 h0 = __floats2half2_rn(o[nt][0] * i0, o[nt][1] * i0);
        __half2 h1 = __floats2half2_rn(o[nt][2] * i1, o[nt][3] * i1);
        *(uint32_t*)&O[(size_t)qrow_g * DIM + col] = *(uint32_t*)&h0;
        *(uint32_t*)&O[(size_t)(qrow_g + 8) * DIM + col] = *(uint32_t*)&h1;
    }
}

// ---------------------------------------------------------------------------
// Launch
// ---------------------------------------------------------------------------
extern "C" void kernel_launch(void* const* d_in, const int* in_sizes, int n_in,
                              void* d_out, int out_size)
{
    const float* x  = (const float*)d_in[0];
    const float* wq = (const float*)d_in[1];
    const float* wk = (const float*)d_in[2];
    const float* wv = (const float*)d_in[3];
    const float* wo = (const float*)d_in[4];
    const float* fc = (const float*)d_in[5];
    const float* fs = (const float*)d_in[6];

    __half *Q16, *K16, *V16, *VT, *A16, *X16, *WqkvT, *WoT;
    cudaGetSymbolAddress((void**)&Q16, g_Q16);
    cudaGetSymbolAddress((void**)&K16, g_K16);
    cudaGetSymbolAddress((void**)&V16, g_V16);
    cudaGetSymbolAddress((void**)&VT, g_vT);
    cudaGetSymbolAddress((void**)&A16, g_attn16);
    cudaGetSymbolAddress((void**)&X16, g_x16);
    cudaGetSymbolAddress((void**)&WqkvT, g_wqkvT);
    cudaGetSymbolAddress((void**)&WoT, g_woT);

    // Pre-passes
    convert_half_kernel<<<SEQ * DIM / 4 / 256, 256>>>(x, X16, SEQ * DIM);
    dim3 tb(32, 8);
    transpose_half_kernel<<<dim3(DIM / 32, DIM / 32), tb>>>(wq, WqkvT, DIM, DIM);
    transpose_half_kernel<<<dim3(KVDIM / 32, DIM / 32), tb>>>(
        wk, WqkvT + (size_t)DIM * DIM, DIM, KVDIM);
    transpose_half_kernel<<<dim3(KVDIM / 32, DIM / 32), tb>>>(
        wv, WqkvT + (size_t)(DIM + KVDIM) * DIM, DIM, KVDIM);
    transpose_half_kernel<<<dim3(DIM / 32, DIM / 32), tb>>>(wo, WoT, DIM, DIM);

    int gsm = 4 * TILE_WORDS * (int)sizeof(uint32_t);
    cudaFuncSetAttribute(gemm_epi_kernel<0>,
                         cudaFuncAttributeMaxDynamicSharedMemorySize, gsm);
    cudaFuncSetAttribute(gemm_epi_kernel<3>,
                         cudaFuncAttributeMaxDynamicSharedMemorySize, gsm);

    // Q scale folds 1/sqrt(128) and log2(e) (base-2 softmax domain)
    const float qscale = 0.08838834764831845f * 1.4426950408889634f;

    // Fused Q|K|V projection: one launch, 768 CTAs of 128 threads.
    gemm_epi_kernel<3><<<dim3(NQKV / GBN, SEQ / GBM), 128, gsm>>>(
        X16, WqkvT, nullptr, Q16, K16, V16, fc, fs, SEQ, NQKV, DIM, qscale);

    // V -> V^T (fp16)
    transpose_h2h_kernel<<<dim3(KVDIM / 32, SEQ / 32), tb>>>(V16, VT, SEQ, KVDIM);

    // Flash attention (pipelined, base-2 softmax) -> fp16 attn
    int fsm = FLASH_SMEM_W * (int)sizeof(uint32_t);
    cudaFuncSetAttribute(flash_kernel,
                         cudaFuncAttributeMaxDynamicSharedMemorySize, fsm);
    flash_kernel<<<dim3(SEQ / FBR, NH), 128, fsm>>>(Q16, K16, VT, A16);

    // Output projection -> d_out (fp32)
    gemm_epi_kernel<0><<<dim3(DIM / GBN, SEQ / GBM), 128, gsm>>>(
        A16, WoT, (float*)d_out, nullptr, nullptr, nullptr, nullptr, nullptr,
        SEQ, DIM, DIM, 1.0f);
}